// round 1
// baseline (speedup 1.0000x reference)
#include <cuda_runtime.h>

#define BB 4
#define SS 512
#define HH 128
#define RR 4   // output rows per block

__global__ __launch_bounds__(HH) void align_kernel(
    const float* __restrict__ x, const float* __restrict__ ref,
    const float* __restrict__ Wa, const float* __restrict__ Wb,
    const float* __restrict__ b1, const float* __restrict__ W2,
    const float* __restrict__ b2, const float* __restrict__ Wp1,
    const float* __restrict__ bp1, const float* __restrict__ Wp2,
    const float* __restrict__ bp2, float* __restrict__ out)
{
    const int blk   = blockIdx.x;
    const int b     = blk / (SS / RR);
    const int chunk = blk % (SS / RR);
    const int t0    = chunk * RR;
    const int h     = threadIdx.x;

    __shared__ float xs[RR + 1][HH];
    __shared__ float rs[RR + 1][HH];

    // rows t0-1 .. t0+RR-1  (local row r <-> global t0-1+r); clamp t=-1 to 0 (unused)
    #pragma unroll
    for (int r = 0; r < RR + 1; r++) {
        int t  = t0 - 1 + r;
        int tc = t < 0 ? 0 : t;
        xs[r][h] = x[(b * SS + tc) * HH + h];
        rs[r][h] = ref[(b * SS + tc) * HH + h];
    }
    __syncthreads();

    // accumulators: a[r] = (x_row_r @ Wa)[h] + b1[h], c[r] = ref_row_r @ Wb,
    // p[i] = relu(x_row(t0+i) @ Wp1 + bp1)[h]
    float a[RR + 1], c[RR + 1], p[RR];
    const float bb1 = b1[h];
    const float bbp1 = bp1[h];
    #pragma unroll
    for (int r = 0; r <= RR; r++) { a[r] = bb1; c[r] = 0.0f; }
    #pragma unroll
    for (int r = 0; r < RR; r++) p[r] = bbp1;

    #pragma unroll 4
    for (int k = 0; k < HH; k++) {
        const float wa = Wa[k * HH + h];
        const float wb = Wb[k * HH + h];
        const float wp = Wp1[k * HH + h];
        #pragma unroll
        for (int r = 0; r <= RR; r++) {
            a[r] = fmaf(xs[r][k], wa, a[r]);
            c[r] = fmaf(rs[r][k], wb, c[r]);
        }
        #pragma unroll
        for (int r = 0; r < RR; r++)
            p[r] = fmaf(xs[r + 1][k], wp, p[r]);
    }
    #pragma unroll
    for (int r = 0; r < RR; r++) p[r] = fmaxf(p[r], 0.0f);

    const float w2   = W2[h];
    const float wp20 = Wp2[h * 3 + 0];
    const float wp21 = Wp2[h * 3 + 1];
    const float wp22 = Wp2[h * 3 + 2];

    __shared__ float red[4][6];   // per-warp partials
    __shared__ float rowvals[2];  // [op_code, alpha]

    const int wid  = h >> 5;
    const int lane = h & 31;

    for (int i = 0; i < RR; i++) {
        const int t = t0 + i;
        // a/c local index: i+1 <-> row t, i <-> row t-1
        float v[6];
        v[0] = fmaxf(a[i + 1] + c[i + 1], 0.0f) * w2;  // A[t, t]
        v[1] = fmaxf(a[i]     + c[i + 1], 0.0f) * w2;  // A[t-1, t]   (insert)
        v[2] = fmaxf(a[i + 1] + c[i],     0.0f) * w2;  // A[t, t-1]   (delete)
        v[3] = p[i] * wp20;
        v[4] = p[i] * wp21;
        v[5] = p[i] * wp22;

        #pragma unroll
        for (int j = 0; j < 6; j++) {
            float s = v[j];
            s += __shfl_xor_sync(0xffffffffu, s, 16);
            s += __shfl_xor_sync(0xffffffffu, s, 8);
            s += __shfl_xor_sync(0xffffffffu, s, 4);
            s += __shfl_xor_sync(0xffffffffu, s, 2);
            s += __shfl_xor_sync(0xffffffffu, s, 1);
            v[j] = s;
        }
        if (lane == 0) {
            #pragma unroll
            for (int j = 0; j < 6; j++) red[wid][j] = v[j];
        }
        __syncthreads();

        if (h == 0) {
            float s[6];
            #pragma unroll
            for (int j = 0; j < 6; j++)
                s[j] = red[0][j] + red[1][j] + red[2][j] + red[3][j];

            float op_code, alpha;
            const float Ad = 1.0f / (1.0f + expf(-(s[0] + b2[0])));
            if (t == 0) {
                op_code = -1.0f;   // plain copy of x[:,0]
                alpha   = 0.0f;
            } else {
                const float Ai   = 1.0f / (1.0f + expf(-(s[1] + b2[0])));
                const float Adel = 1.0f / (1.0f + expf(-(s[2] + b2[0])));
                const float l0 = s[3] + bp2[0];
                const float l1 = s[4] + bp2[1];
                const float l2 = s[5] + bp2[2];
                const float mx  = fmaxf(l0, fmaxf(l1, l2));
                const float lse = mx + logf(expf(l0 - mx) + expf(l1 - mx) + expf(l2 - mx));
                const float P0 = l0 - lse, P1 = l1 - lse, P2 = l2 - lse;
                const float m   = Ad   * P0;
                const float ins = Ai   * P1;
                const float del = Adel * P2;
                int op;
                if (m >= ins && m >= del) op = 0;      // first-max tie-break == jnp.argmax
                else if (ins >= del)      op = 1;
                else                      op = 2;
                op_code = (float)op;
                alpha   = Ad;
            }
            rowvals[0] = op_code;
            rowvals[1] = alpha;
        }
        __syncthreads();

        const float fop   = rowvals[0];
        const float alpha = rowvals[1];
        float o;
        if (fop < -0.5f)      o = xs[i + 1][h];                                    // t == 0
        else if (fop < 0.5f)  o = (1.0f - alpha) * xs[i + 1][h] + alpha * rs[i + 1][h];
        else if (fop < 1.5f)  o = rs[i + 1][h];                                    // insert
        else                  o = xs[i][h];                                        // delete: x[t-1]
        out[(b * SS + t) * HH + h] = o;
        __syncthreads();  // protect red/rowvals before next iteration
    }
}

extern "C" void kernel_launch(void* const* d_in, const int* in_sizes, int n_in,
                              void* d_out, int out_size) {
    const float* x   = (const float*)d_in[0];
    const float* ref = (const float*)d_in[1];
    const float* Wa  = (const float*)d_in[2];
    const float* Wb  = (const float*)d_in[3];
    const float* b1  = (const float*)d_in[4];
    const float* W2  = (const float*)d_in[5];
    const float* b2  = (const float*)d_in[6];
    const float* Wp1 = (const float*)d_in[7];
    const float* bp1 = (const float*)d_in[8];
    const float* Wp2 = (const float*)d_in[9];
    const float* bp2 = (const float*)d_in[10];

    dim3 grid(BB * (SS / RR));  // 512 blocks
    dim3 block(HH);             // 128 threads
    align_kernel<<<grid, block>>>(x, ref, Wa, Wb, b1, W2, b2,
                                  Wp1, bp1, Wp2, bp2, (float*)d_out);
}